// round 3
// baseline (speedup 1.0000x reference)
#include <cuda_runtime.h>
#include <cuda_bf16.h>

// HANMeta: B=512, P=64, K=8, D=512, T=50000
// Two-phase split to separate L2 working sets:
//   Phase 1: attention weights (inputs table only, 67MB -> L2-resident)
//   Phase 2: weighted title aggregation (title table only, 102MB -> mostly L2)

#define HM_B 512
#define HM_P 64
#define HM_K 8
#define HM_D 512
#define HM_ROWS (HM_B * HM_P)   // 32768
#define HM_BLOCK 128            // one float4 lane per thread covers D=512

// Scratch: per-(row,k) softmax weights. 32768*8*4B = 1 MB.
__device__ float g_w[HM_ROWS * HM_K];

// ---------------- Phase 1: dots + softmax + focal copy ----------------
__global__ __launch_bounds__(HM_BLOCK, 12) void han_attn_kernel(
    const float* __restrict__ inputs,       // [B,P,D]
    const int*   __restrict__ nbr_batch,    // [B,P,K]
    const int*   __restrict__ nbr_job,      // [B,P,K]
    const int*   __restrict__ nbr_mask,     // [B,P,K]
    float*       __restrict__ out)          // [B*P, 2D]
{
    const int row = blockIdx.x;
    const int tid = threadIdx.x;

    __shared__ __align__(16) int s_off[HM_K];
    __shared__ __align__(16) int s_mk[HM_K];
    __shared__ float s_ws[4][HM_K];

    if (tid < HM_K) {
        const int base = row * HM_K + tid;
        s_off[tid] = (nbr_batch[base] * HM_P + nbr_job[base]) * HM_D;
        s_mk[tid]  = nbr_mask[base];
    }
    __syncthreads();

    const float4 f = reinterpret_cast<const float4*>(inputs + row * HM_D)[tid];

    const int4 mkv0 = *reinterpret_cast<const int4*>(&s_mk[0]);
    const int4 mkv1 = *reinterpret_cast<const int4*>(&s_mk[4]);
    const int4 ofv0 = *reinterpret_cast<const int4*>(&s_off[0]);
    const int4 ofv1 = *reinterpret_cast<const int4*>(&s_off[4]);
    const int mk[HM_K]  = {mkv0.x, mkv0.y, mkv0.z, mkv0.w, mkv1.x, mkv1.y, mkv1.z, mkv1.w};
    const int off[HM_K] = {ofv0.x, ofv0.y, ofv0.z, ofv0.w, ofv1.x, ofv1.y, ofv1.z, ofv1.w};

    // Masked dot partials (MLP=8; skip gather when mask==0)
    float part[HM_K];
    #pragma unroll
    for (int k = 0; k < HM_K; k++) {
        part[k] = 0.0f;
        if (mk[k]) {
            float4 v = reinterpret_cast<const float4*>(inputs + off[k])[tid];
            part[k] = f.x * v.x + f.y * v.y + f.z * v.z + f.w * v.w;
        }
    }

    #pragma unroll
    for (int sh = 16; sh > 0; sh >>= 1) {
        #pragma unroll
        for (int k = 0; k < HM_K; k++)
            part[k] += __shfl_xor_sync(0xffffffffu, part[k], sh);
    }

    const int warp = tid >> 5, lane = tid & 31;
    if (lane == 0) {
        #pragma unroll
        for (int k = 0; k < HM_K; k++) s_ws[warp][k] = part[k];
    }
    __syncthreads();

    // Thread 0 computes softmax weights and writes them to scratch.
    // Mirrors reference exactly (incl. all-masked -> all-zero row).
    if (tid == 0) {
        float logit[HM_K], w[HM_K];
        float m = -3.0e38f;
        #pragma unroll
        for (int k = 0; k < HM_K; k++) {
            float s = s_ws[0][k] + s_ws[1][k] + s_ws[2][k] + s_ws[3][k];
            logit[k] = mk[k] ? s : -1e9f;
            m = fmaxf(m, logit[k]);
        }
        float sum = 0.0f;
        #pragma unroll
        for (int k = 0; k < HM_K; k++) {
            w[k] = __expf(logit[k] - m);
            sum += w[k];
        }
        const float inv = 1.0f / sum;
        #pragma unroll
        for (int k = 0; k < HM_K; k++)
            w[k] = mk[k] ? (w[k] * inv) : 0.0f;

        float4* gw = reinterpret_cast<float4*>(&g_w[row * HM_K]);
        __stcs(gw + 0, make_float4(w[0], w[1], w[2], w[3]));
        __stcs(gw + 1, make_float4(w[4], w[5], w[6], w[7]));
    }

    // Focal half of the output (we already hold f) — streaming store.
    __stcs(reinterpret_cast<float4*>(out + row * (2 * HM_D)) + tid, f);
}

// ---------------- Phase 2: weighted title aggregation ----------------
__global__ __launch_bounds__(HM_BLOCK, 12) void han_aggr_kernel(
    const float* __restrict__ title,        // [T,D]
    const int*   __restrict__ nbr_title,    // [B,P,K]
    float*       __restrict__ out)          // [B*P, 2D]
{
    const int row = blockIdx.x;
    const int tid = threadIdx.x;

    __shared__ __align__(16) float s_w[HM_K];
    __shared__ __align__(16) int   s_nt[HM_K];

    if (tid < HM_K) {
        s_w[tid]  = __ldcs(&g_w[row * HM_K + tid]);   // read-once weights
        s_nt[tid] = nbr_title[row * HM_K + tid];
    }
    __syncthreads();

    const float4 wv0 = *reinterpret_cast<const float4*>(&s_w[0]);
    const float4 wv1 = *reinterpret_cast<const float4*>(&s_w[4]);
    const float w[HM_K] = {wv0.x, wv0.y, wv0.z, wv0.w, wv1.x, wv1.y, wv1.z, wv1.w};
    const int4 ntv0 = *reinterpret_cast<const int4*>(&s_nt[0]);
    const int4 ntv1 = *reinterpret_cast<const int4*>(&s_nt[4]);
    const int nt[HM_K] = {ntv0.x, ntv0.y, ntv0.z, ntv0.w, ntv1.x, ntv1.y, ntv1.z, ntv1.w};

    // Masked slots have weight exactly 0 -> skip the gather entirely.
    float4 acc = make_float4(0.f, 0.f, 0.f, 0.f);
    #pragma unroll
    for (int k = 0; k < HM_K; k++) {
        if (w[k] != 0.0f) {
            float4 v = reinterpret_cast<const float4*>(title + nt[k] * HM_D)[tid];
            acc.x += w[k] * v.x;
            acc.y += w[k] * v.y;
            acc.z += w[k] * v.z;
            acc.w += w[k] * v.w;
        }
    }

    __stcs(reinterpret_cast<float4*>(out + row * (2 * HM_D)) + HM_BLOCK + tid, acc);
}

extern "C" void kernel_launch(void* const* d_in, const int* in_sizes, int n_in,
                              void* d_out, int out_size)
{
    const float* inputs    = (const float*)d_in[0];
    const float* title     = (const float*)d_in[1];
    const int*   nbr_batch = (const int*)  d_in[2];
    const int*   nbr_job   = (const int*)  d_in[3];
    const int*   nbr_title = (const int*)  d_in[4];
    const int*   nbr_mask  = (const int*)  d_in[5];
    float*       out       = (float*)d_out;

    han_attn_kernel<<<HM_ROWS, HM_BLOCK>>>(inputs, nbr_batch, nbr_job, nbr_mask, out);
    han_aggr_kernel<<<HM_ROWS, HM_BLOCK>>>(title, nbr_title, out);
}

// round 4
// speedup vs baseline: 1.2249x; 1.2249x over previous
#include <cuda_runtime.h>
#include <cuda_bf16.h>

// HANMeta: B=512, P=64, K=8, D=512, T=50000
// Two-phase (L2 working-set separation) + warp-per-row (no barriers, high MLP).

#define HM_B 512
#define HM_P 64
#define HM_K 8
#define HM_D 512
#define HM_D4 (HM_D / 4)            // 128 float4 per row
#define HM_ROWS (HM_B * HM_P)       // 32768
#define HM_WARPS 8
#define HM_THREADS (HM_WARPS * 32)  // 256
#define HM_GRID (HM_ROWS / HM_WARPS)// 4096
#define HM_CHUNKS 4                 // 4 chunks of 32 float4 cover D=512
#define FULL 0xffffffffu

// Per-(row,k) softmax weights scratch: 1 MB.
__device__ float g_w[HM_ROWS * HM_K];

// ---------------- Phase 1: dots + softmax + focal copy (inputs only) --------
__global__ __launch_bounds__(HM_THREADS, 4) void han_attn_kernel(
    const float* __restrict__ inputs,
    const int*   __restrict__ nbr_batch,
    const int*   __restrict__ nbr_job,
    const int*   __restrict__ nbr_mask,
    float*       __restrict__ out)
{
    const int warp = threadIdx.x >> 5;
    const int lane = threadIdx.x & 31;
    const int row  = blockIdx.x * HM_WARPS + warp;

    // Lanes 0..7 load this row's indices; broadcast via shuffles.
    int mk_l = 0, off_l = 0;
    if (lane < HM_K) {
        const int base = row * HM_K + lane;
        mk_l  = nbr_mask[base];
        off_l = (nbr_batch[base] * HM_P + nbr_job[base]) * HM_D4;  // float4 units
    }
    int mk[HM_K], off[HM_K];
    #pragma unroll
    for (int k = 0; k < HM_K; k++) {
        mk[k]  = __shfl_sync(FULL, mk_l, k);
        off[k] = __shfl_sync(FULL, off_l, k);
    }

    const float4* in4 = reinterpret_cast<const float4*>(inputs);
    float4* o4 = reinterpret_cast<float4*>(out) + (long long)row * (2 * HM_D4);

    // Dot products, chunked over D; focal half streamed to out as we go.
    float part[HM_K] = {0.f, 0.f, 0.f, 0.f, 0.f, 0.f, 0.f, 0.f};
    const int fbase = row * HM_D4 + lane;
    #pragma unroll
    for (int c = 0; c < HM_CHUNKS; c++) {
        const float4 fv = in4[fbase + c * 32];
        __stcs(&o4[c * 32 + lane], fv);
        #pragma unroll
        for (int k = 0; k < HM_K; k++) {
            if (mk[k]) {
                const float4 nv = in4[off[k] + c * 32 + lane];
                part[k] = fmaf(fv.x, nv.x,
                          fmaf(fv.y, nv.y,
                          fmaf(fv.z, nv.z,
                          fmaf(fv.w, nv.w, part[k]))));
            }
        }
    }

    // Warp xor-shuffle reduction: all lanes end with full sums.
    #pragma unroll
    for (int sh = 16; sh > 0; sh >>= 1) {
        #pragma unroll
        for (int k = 0; k < HM_K; k++)
            part[k] += __shfl_xor_sync(FULL, part[k], sh);
    }

    // Softmax (redundant per lane; mirrors reference incl. all-masked -> 0 row).
    float logit[HM_K], w[HM_K];
    float m = -3.0e38f;
    #pragma unroll
    for (int k = 0; k < HM_K; k++) {
        logit[k] = mk[k] ? part[k] : -1e9f;
        m = fmaxf(m, logit[k]);
    }
    float sum = 0.0f;
    #pragma unroll
    for (int k = 0; k < HM_K; k++) {
        w[k] = __expf(logit[k] - m);
        sum += w[k];
    }
    const float inv = 1.0f / sum;
    #pragma unroll
    for (int k = 0; k < HM_K; k++)
        w[k] = mk[k] ? (w[k] * inv) : 0.0f;

    if (lane < HM_K)
        __stcs(&g_w[row * HM_K + lane], w[lane]);
}

// ---------------- Phase 2: weighted title aggregation (title only) ----------
__global__ __launch_bounds__(HM_THREADS, 4) void han_aggr_kernel(
    const float* __restrict__ title,
    const int*   __restrict__ nbr_title,
    float*       __restrict__ out)
{
    const int warp = threadIdx.x >> 5;
    const int lane = threadIdx.x & 31;
    const int row  = blockIdx.x * HM_WARPS + warp;

    float w_l = 0.0f; int nt_l = 0;
    if (lane < HM_K) {
        const int base = row * HM_K + lane;
        w_l  = __ldcs(&g_w[base]);       // read-once weights
        nt_l = nbr_title[base] * HM_D4;  // float4 units
    }
    float w[HM_K]; int nt[HM_K];
    #pragma unroll
    for (int k = 0; k < HM_K; k++) {
        w[k]  = __shfl_sync(FULL, w_l, k);
        nt[k] = __shfl_sync(FULL, nt_l, k);
    }

    const float4* t4 = reinterpret_cast<const float4*>(title);
    float4* o4 = reinterpret_cast<float4*>(out)
               + (long long)row * (2 * HM_D4) + HM_D4;

    // Weight==0 (masked) -> skip the gather entirely.
    #pragma unroll
    for (int c = 0; c < HM_CHUNKS; c++) {
        float4 acc = make_float4(0.f, 0.f, 0.f, 0.f);
        #pragma unroll
        for (int k = 0; k < HM_K; k++) {
            if (w[k] != 0.0f) {
                const float4 tv = t4[nt[k] + c * 32 + lane];
                acc.x = fmaf(w[k], tv.x, acc.x);
                acc.y = fmaf(w[k], tv.y, acc.y);
                acc.z = fmaf(w[k], tv.z, acc.z);
                acc.w = fmaf(w[k], tv.w, acc.w);
            }
        }
        __stcs(&o4[c * 32 + lane], acc);
    }
}

extern "C" void kernel_launch(void* const* d_in, const int* in_sizes, int n_in,
                              void* d_out, int out_size)
{
    const float* inputs    = (const float*)d_in[0];
    const float* title     = (const float*)d_in[1];
    const int*   nbr_batch = (const int*)  d_in[2];
    const int*   nbr_job   = (const int*)  d_in[3];
    const int*   nbr_title = (const int*)  d_in[4];
    const int*   nbr_mask  = (const int*)  d_in[5];
    float*       out       = (float*)d_out;

    han_attn_kernel<<<HM_GRID, HM_THREADS>>>(inputs, nbr_batch, nbr_job, nbr_mask, out);
    han_aggr_kernel<<<HM_GRID, HM_THREADS>>>(title, nbr_title, out);
}